// round 5
// baseline (speedup 1.0000x reference)
#include <cuda_runtime.h>
#include <cstdint>
#include <cstddef>

#define T_DIM 2048
#define B_DIM 32
#define E_DIM 512
#define N_DIM 512
#define K_DIM 512
#define M_DIM (T_DIM * B_DIM)

#define SA_SCALE 33554432.0f    // 2^25
#define SB_SCALE 67108864.0f    // 2^26

// ---------------- device scratch ----------------
__device__ float g_w[M_DIM];
__device__ float g_part[M_DIM * 4];
__device__ int   g_len[B_DIM];
__device__ int   g_nrows[B_DIM];
__device__ int   g_rt0[B_DIM * T_DIM];
__device__ int   g_rt1[B_DIM * T_DIM];
__device__ float g_rc0[B_DIM * T_DIM];
__device__ float g_rc1[B_DIM * T_DIM];
__device__ float g_rmult[B_DIM * T_DIM];
// B digit planes, packed as the exact smem image:
// [strip 4][chunk 16] x (128 n x 8 ku x 4 planes) u32  (plane 3 = zero pad)
__device__ uint32_t g_Bd[4 * 16 * 4096];

// ---------------- helpers ----------------
__device__ __forceinline__ void imma(int* c, const uint32_t* a4, uint32_t b0, uint32_t b1) {
    asm("mma.sync.aligned.m16n8k32.row.col.s32.s8.s8.s32 "
        "{%0,%1,%2,%3}, {%4,%5,%6,%7}, {%8,%9}, {%0,%1,%2,%3};"
        : "+r"(c[0]), "+r"(c[1]), "+r"(c[2]), "+r"(c[3])
        : "r"(a4[0]), "r"(a4[1]), "r"(a4[2]), "r"(a4[3]), "r"(b0), "r"(b1));
}
// pack plane p byte of 4 biased u32s (k ascending -> LSB first), unbias
__device__ __forceinline__ uint32_t plane4(uint32_t u0, uint32_t u1, uint32_t u2,
                                           uint32_t u3, int p) {
    uint32_t sel = (uint32_t)p | ((uint32_t)(p + 4) << 4);
    uint32_t t01 = __byte_perm(u0, u1, sel);
    uint32_t t23 = __byte_perm(u2, u3, sel);
    return __byte_perm(t01, t23, 0x5410) ^ 0x80808080u;
}

// ---------------- K0: mask dtype detection + lengths ------------------------
__global__ void k0_mask(const void* __restrict__ mask) {
    __shared__ int flags[3];
    int tid = threadIdx.x;
    if (tid < 3) flags[tid] = 0;
    __syncthreads();
    const unsigned* dw = (const unsigned*)mask;
    for (int i = tid; i < 16384; i += blockDim.x) {
        unsigned d = dw[i];
        if (d != 0u) {
            if (d == 1u)                flags[0] = 1;
            else if (d == 0x3F800000u)  flags[1] = 1;
            else                        flags[2] = 1;
        }
    }
    __syncthreads();
    int kind = flags[2] ? 2 : (flags[1] ? 1 : 0);
    int warp = tid >> 5, lane = tid & 31;
    int cnt = 0;
    if (kind == 2) {
        const unsigned char* p = (const unsigned char*)mask + warp * T_DIM;
        for (int t = lane; t < T_DIM; t += 32) cnt += (p[t] == 0);
    } else {
        const unsigned* p = dw + (size_t)warp * T_DIM;
        for (int t = lane; t < T_DIM; t += 32) cnt += (p[t] == 0u);
    }
    for (int o = 16; o > 0; o >>= 1) cnt += __shfl_down_sync(0xffffffffu, cnt, o);
    if (lane == 0) g_len[warp] = cnt;
}

// ---------------- K_prepB: quantize + digit-split + frag-pack W1 ------------
// grid (chunk 16, strip 4), block 1024: ku = tid>>7, n = tid&127
__global__ void k_prepB(const float* __restrict__ W1) {
    const int chunk = blockIdx.x, strip = blockIdx.y;
    const int ku = threadIdx.x >> 7, n = threadIdx.x & 127;
    const int kb = chunk * 32 + ku * 4;
    const int ng = strip * 128 + n;
    uint32_t u[4];
#pragma unroll
    for (int e = 0; e < 4; e++) {
        int bi = __float2int_rn(W1[(size_t)(kb + e) * N_DIM + ng] * SB_SCALE);
        u[e] = (uint32_t)bi + 0x00808080u;
    }
    uint32_t* dst = g_Bd + (size_t)(strip * 16 + chunk) * 4096
                  + ((uint32_t)n * 8 + ((uint32_t)ku ^ (n & 7))) * 4;
    dst[0] = plane4(u[0], u[1], u[2], u[3], 0);
    dst[1] = plane4(u[0], u[1], u[2], u[3], 1);
    dst[2] = plane4(u[0], u[1], u[2], u[3], 2);
    dst[3] = 0u;
}

// ---------------- K1: exact s8-sliced IMMA GEMM + partial epilogue ----------
// smem u32 layout: sA 2x2048 | sB 2x4096 | sb1 128f | sw2 128f | red 128f
#define SM_U32 (4096 + 8192 + 128 + 128 + 128)
#define SM_BYTES (SM_U32 * 4)

__global__ __launch_bounds__(256) void k1_imma(
    const float* __restrict__ A,
    const float* __restrict__ b1g,
    const float* __restrict__ w2g)
{
    extern __shared__ uint32_t sm[];
    uint32_t* sA = sm;                     // 2 x 2048
    uint32_t* sB = sm + 4096;              // 2 x 4096
    float* sb1 = (float*)(sm + 12288);
    float* sw2 = (float*)(sm + 12416);
    float* red = (float*)(sm + 12544);     // [64][2]

    const int tid = threadIdx.x;
    const int warp = tid >> 5, lane = tid & 31;
    const int wm = warp >> 1, wn = warp & 1;
    const int g = lane >> 2, tig = lane & 3;
    const int strip = blockIdx.x;
    const int m0 = blockIdx.y * 64;

    if (tid < 128) {
        sb1[tid] = b1g[strip * 128 + tid];
        sw2[tid] = w2g[strip * 128 + tid];
    }

    // A loader: idx {tid, tid+256} -> (m, ku); idx2 = m+32, same ku
    const int m_a = tid >> 3, ku_a = tid & 7;
    const float* pA0 = A + (size_t)(m0 + m_a) * K_DIM + ku_a * 4;
    const float* pA1 = pA0 + (size_t)32 * K_DIM;
    const uint32_t dA0 = ((uint32_t)m_a * 8 + ((uint32_t)ku_a ^ (m_a & 7))) * 4;
    const uint32_t dA1 = dA0 + 1024;
    const uint32_t* pBsrc = g_Bd + (size_t)strip * 16 * 4096;

    int S2[8][4], S3[8][4], S4[8][4], S5[8][4];
#pragma unroll
    for (int nt = 0; nt < 8; nt++)
#pragma unroll
        for (int q = 0; q < 4; q++) { S2[nt][q] = 0; S3[nt][q] = 0; S4[nt][q] = 0; S5[nt][q] = 0; }

    float4 pa0 = *(const float4*)(pA0);
    float4 pa1 = *(const float4*)(pA1);
    uint4 pb[4];
#pragma unroll
    for (int r = 0; r < 4; r++)
        pb[r] = ((const uint4*)pBsrc)[tid + 256 * r];

    const int row0 = wm * 16 + g, row1 = row0 + 8;
    const uint32_t gA0 = row0 * 8 + (tig ^ (row0 & 7));
    const uint32_t gA1 = row1 * 8 + (tig ^ (row1 & 7));
    const uint32_t gA2 = row0 * 8 + ((tig + 4) ^ (row0 & 7));
    const uint32_t gA3 = row1 * 8 + ((tig + 4) ^ (row1 & 7));

    for (int c = 0; c < 16; c++) {
        const int buf = c & 1;
        // store A digits (biased bytes -> signed planes), frag-packed
        {
            uint32_t* d0 = sA + buf * 2048 + dA0;
            uint32_t u0 = (uint32_t)__float2int_rn(pa0.x * SA_SCALE) + 0x80808080u;
            uint32_t u1 = (uint32_t)__float2int_rn(pa0.y * SA_SCALE) + 0x80808080u;
            uint32_t u2 = (uint32_t)__float2int_rn(pa0.z * SA_SCALE) + 0x80808080u;
            uint32_t u3 = (uint32_t)__float2int_rn(pa0.w * SA_SCALE) + 0x80808080u;
            uint4 v = make_uint4(plane4(u0,u1,u2,u3,0), plane4(u0,u1,u2,u3,1),
                                 plane4(u0,u1,u2,u3,2), plane4(u0,u1,u2,u3,3));
            *(uint4*)d0 = v;
            uint32_t* d1 = sA + buf * 2048 + dA1;
            u0 = (uint32_t)__float2int_rn(pa1.x * SA_SCALE) + 0x80808080u;
            u1 = (uint32_t)__float2int_rn(pa1.y * SA_SCALE) + 0x80808080u;
            u2 = (uint32_t)__float2int_rn(pa1.z * SA_SCALE) + 0x80808080u;
            u3 = (uint32_t)__float2int_rn(pa1.w * SA_SCALE) + 0x80808080u;
            v = make_uint4(plane4(u0,u1,u2,u3,0), plane4(u0,u1,u2,u3,1),
                           plane4(u0,u1,u2,u3,2), plane4(u0,u1,u2,u3,3));
            *(uint4*)d1 = v;
        }
#pragma unroll
        for (int r = 0; r < 4; r++)
            ((uint4*)(sB + buf * 4096))[tid + 256 * r] = pb[r];
        // prefetch next chunk
        if (c < 15) {
            pa0 = *(const float4*)(pA0 + (c + 1) * 32);
            pa1 = *(const float4*)(pA1 + (c + 1) * 32);
#pragma unroll
            for (int r = 0; r < 4; r++)
                pb[r] = ((const uint4*)(pBsrc + (size_t)(c + 1) * 4096))[tid + 256 * r];
        }
        __syncthreads();

        const uint4* sA4 = (const uint4*)(sA + buf * 2048);
        const uint4* sB4 = (const uint4*)(sB + buf * 4096);
        uint4 fa0 = sA4[gA0], fa1 = sA4[gA1], fa2 = sA4[gA2], fa3 = sA4[gA3];
        uint32_t A0[4] = {fa0.x, fa1.x, fa2.x, fa3.x};
        uint32_t A1[4] = {fa0.y, fa1.y, fa2.y, fa3.y};
        uint32_t A2[4] = {fa0.z, fa1.z, fa2.z, fa3.z};
        uint32_t A3[4] = {fa0.w, fa1.w, fa2.w, fa3.w};
#pragma unroll
        for (int nt = 0; nt < 8; nt++) {
            const int n = wn * 64 + nt * 8 + g;
            uint4 b0v = sB4[n * 8 + (tig ^ (n & 7))];
            uint4 b1v = sB4[n * 8 + ((tig + 4) ^ (n & 7))];
            imma(S2[nt], A0, b0v.z, b1v.z);
            imma(S2[nt], A1, b0v.y, b1v.y);
            imma(S2[nt], A2, b0v.x, b1v.x);
            imma(S3[nt], A1, b0v.z, b1v.z);
            imma(S3[nt], A2, b0v.y, b1v.y);
            imma(S3[nt], A3, b0v.x, b1v.x);
            imma(S4[nt], A2, b0v.z, b1v.z);
            imma(S4[nt], A3, b0v.y, b1v.y);
            imma(S5[nt], A3, b0v.z, b1v.z);
        }
    }

    // epilogue: h = S2*2^-35 + S3*2^-27 + S4*2^-19 + S5*2^-11
    const float c35 = 2.9103830456733704e-11f;
    const float c27 = 7.450580596923828e-9f;
    const float c19 = 1.9073486328125e-6f;
    const float c11 = 4.8828125e-4f;
    float aR0 = 0.f, aR1 = 0.f;
#pragma unroll
    for (int nt = 0; nt < 8; nt++) {
        const int colb = wn * 64 + nt * 8 + tig * 2;
#pragma unroll
        for (int q = 0; q < 4; q++) {
            float h = fmaf((float)S2[nt][q], c35,
                      fmaf((float)S3[nt][q], c27,
                      fmaf((float)S4[nt][q], c19, (float)S5[nt][q] * c11)));
            const int col = colb + (q & 1);
            float r = fmaxf(h + sb1[col], 0.f) * sw2[col];
            if (q < 2) aR0 += r; else aR1 += r;
        }
    }
    aR0 += __shfl_xor_sync(0xffffffffu, aR0, 1);
    aR0 += __shfl_xor_sync(0xffffffffu, aR0, 2);
    aR1 += __shfl_xor_sync(0xffffffffu, aR1, 1);
    aR1 += __shfl_xor_sync(0xffffffffu, aR1, 2);
    __syncthreads();
    if (tig == 0) {
        red[row0 * 2 + wn] = aR0;
        red[row1 * 2 + wn] = aR1;
    }
    __syncthreads();
    if (tid < 64)
        g_part[(size_t)(m0 + tid) * 4 + strip] = red[tid * 2] + red[tid * 2 + 1];
}

// ---------------- K1b: combine strips (fixed order) + sigmoid ---------------
__global__ void k1b(const float* __restrict__ b2g) {
    const int m = blockIdx.x * 256 + threadIdx.x;
    float4 p = *(const float4*)(g_part + (size_t)m * 4);
    float s = ((p.x + p.y) + p.z) + p.w + b2g[0];
    g_w[m] = 1.0f / (1.0f + expf(-s));
}

// ---------------- K2: scalar CIF scan per batch -----------------------------
__global__ void k2_scan(float* __restrict__ out_marks,
                        float* __restrict__ out_quantity,
                        int write_extras)
{
    const int b = blockIdx.x;
    const int lane = threadIdx.x;
    const int L = g_len[b];

    float prev_w = 0.f, quantity = 0.f, seg_c0 = 0.f, last_w = 0.f;
    int seg_t0 = 0, r = 0;

    for (int chunk = 0; chunk < T_DIM; chunk += 32) {
        float wv = g_w[(chunk + lane) * B_DIM + b];
        float mymark = 0.f;
#pragma unroll 1
        for (int j = 0; j < 32; j++) {
            const int t = chunk + j;
            float w = __shfl_sync(0xffffffffu, wv, j);
            float mark = 0.f;
            if (t < L) {
                quantity += w;
                if (t == 0) seg_c0 = w;
                bool fired = (prev_w + w >= 1.0f);
                if (fired) {
                    float remained = 1.0f - prev_w;
                    if (lane == 0) {
                        int idx = b * T_DIM + r;
                        g_rt0[idx] = seg_t0; g_rt1[idx] = t;
                        g_rc0[idx] = seg_c0; g_rc1[idx] = remained;
                        g_rmult[idx] = 1.0f;
                    }
                    r++;
                    prev_w = w - remained;
                    seg_t0 = t;
                    seg_c0 = w - remained;
                    mark = 1.f;
                } else {
                    prev_w = w + prev_w;
                }
                last_w = w;
            } else if (t == L) {
                if (prev_w > 0.6f) {
                    if (lane == 0) {
                        int idx = b * T_DIM + r;
                        g_rt0[idx] = seg_t0; g_rt1[idx] = L - 1;
                        g_rc0[idx] = seg_c0; g_rc1[idx] = last_w;
                        g_rmult[idx] = 1.0f / (prev_w + 1e-10f);
                    }
                    r++;
                    mark = 1.f;
                }
            }
            if (lane == j) mymark = mark;
        }
        if (write_extras) out_marks[b * T_DIM + chunk + lane] = mymark;
    }
    if (lane == 0) {
        g_nrows[b] = r;
        if (write_extras) out_quantity[b] = quantity;
    }
}

// ---------------- K3: segment sums in compacted order -----------------------
__global__ __launch_bounds__(128) void k3_rows(
    const float* __restrict__ x,
    float* __restrict__ out_cif,
    float* __restrict__ out_mask,
    int write_extras)
{
    const int r = blockIdx.x, b = blockIdx.y;
    const int tid = threadIdx.x;
    const int nr = g_nrows[b];

    float4 acc = make_float4(0.f, 0.f, 0.f, 0.f);
    if (r < nr) {
        const int idx = b * T_DIM + r;
        const int t0 = g_rt0[idx], t1 = g_rt1[idx];
        const float c0 = g_rc0[idx], c1 = g_rc1[idx], mult = g_rmult[idx];
        const float* xb = x + (size_t)b * E_DIM + tid * 4;
        const size_t tstride = (size_t)B_DIM * E_DIM;

        float4 v = *(const float4*)(xb + (size_t)t0 * tstride);
        acc.x = c0 * v.x; acc.y = c0 * v.y; acc.z = c0 * v.z; acc.w = c0 * v.w;
        for (int t = t0 + 1; t < t1; t++) {
            float w = g_w[t * B_DIM + b];
            v = *(const float4*)(xb + (size_t)t * tstride);
            acc.x = fmaf(w, v.x, acc.x); acc.y = fmaf(w, v.y, acc.y);
            acc.z = fmaf(w, v.z, acc.z); acc.w = fmaf(w, v.w, acc.w);
        }
        if (t1 > t0) {
            v = *(const float4*)(xb + (size_t)t1 * tstride);
            acc.x = fmaf(c1, v.x, acc.x); acc.y = fmaf(c1, v.y, acc.y);
            acc.z = fmaf(c1, v.z, acc.z); acc.w = fmaf(c1, v.w, acc.w);
        }
        acc.x *= mult; acc.y *= mult; acc.z *= mult; acc.w *= mult;
    }
    *(float4*)(out_cif + ((size_t)(b * T_DIM + r)) * E_DIM + tid * 4) = acc;
    if (write_extras && tid == 0) out_mask[b * T_DIM + r] = (r < nr) ? 1.f : 0.f;
}

// ---------------- launch ----------------------------------------------------
extern "C" void kernel_launch(void* const* d_in, const int* in_sizes, int n_in,
                              void* d_out, int out_size)
{
    const float* enc = (const float*)d_in[0];
    const void*  mask = d_in[1];
    const float* dense_w = (const float*)d_in[2];
    const float* dense_b = (const float*)d_in[3];
    const float* wproj_w = (const float*)d_in[4];
    const float* wproj_b = (const float*)d_in[5];
    float* out = (float*)d_out;

    const int cif_elems = B_DIM * T_DIM * E_DIM;
    const int full = cif_elems + B_DIM * T_DIM + B_DIM + B_DIM * T_DIM;
    const int extras = (out_size >= full) ? 1 : 0;

    float* out_mask   = out + cif_elems;
    float* out_q      = out_mask + B_DIM * T_DIM;
    float* out_marks  = out_q + B_DIM;

    cudaFuncSetAttribute(k1_imma, cudaFuncAttributeMaxDynamicSharedMemorySize, SM_BYTES);

    k0_mask<<<1, 1024>>>(mask);
    k_prepB<<<dim3(16, 4), 1024>>>(dense_w);
    k1_imma<<<dim3(4, M_DIM / 64), 256, SM_BYTES>>>(enc, dense_b, wproj_w);
    k1b<<<M_DIM / 256, 256>>>(wproj_b);
    k2_scan<<<B_DIM, 32>>>(out_marks, out_q, extras);
    k3_rows<<<dim3(T_DIM, B_DIM), 128>>>(enc, out, out_mask, extras);
}

// round 6
// speedup vs baseline: 4.0519x; 4.0519x over previous
#include <cuda_runtime.h>
#include <cstdint>
#include <cstddef>

#define T_DIM 2048
#define B_DIM 32
#define E_DIM 512
#define N_DIM 512
#define K_DIM 512
#define M_DIM (T_DIM * B_DIM)   // 65536 rows, row m = t*B + b

// ---------------- device scratch ----------------
__device__ float g_w[M_DIM];
__device__ int   g_len[B_DIM];
__device__ int   g_nrows[B_DIM];
__device__ int   g_rt0[B_DIM * T_DIM];
__device__ int   g_rt1[B_DIM * T_DIM];
__device__ float g_rc0[B_DIM * T_DIM];
__device__ float g_rc1[B_DIM * T_DIM];
__device__ float g_rmult[B_DIM * T_DIM];

// ---------------- f32x2 helpers ----------------
typedef unsigned long long u64;
__device__ __forceinline__ u64 fma2(u64 a, u64 b, u64 c) {
    u64 d;
    asm("fma.rn.f32x2 %0, %1, %2, %3;" : "=l"(d) : "l"(a), "l"(b), "l"(c));
    return d;
}
__device__ __forceinline__ u64 dupf(float a) {
    u64 d;
    asm("mov.b64 %0, {%1, %1};" : "=l"(d) : "f"(a));
    return d;
}
__device__ __forceinline__ void unpk(u64 v, float& lo, float& hi) {
    asm("mov.b64 {%0, %1}, %2;" : "=f"(lo), "=f"(hi) : "l"(v));
}

// ---------------- K0: mask dtype detection + lengths ------------------------
__global__ void k0_mask(const void* __restrict__ mask) {
    __shared__ int flags[3];
    int tid = threadIdx.x;
    if (tid < 3) flags[tid] = 0;
    __syncthreads();
    const unsigned* dw = (const unsigned*)mask;
    for (int i = tid; i < 16384; i += blockDim.x) {
        unsigned d = dw[i];
        if (d != 0u) {
            if (d == 1u)                flags[0] = 1;
            else if (d == 0x3F800000u)  flags[1] = 1;
            else                        flags[2] = 1;
        }
    }
    __syncthreads();
    int kind = flags[2] ? 2 : (flags[1] ? 1 : 0);
    int warp = tid >> 5, lane = tid & 31;
    int cnt = 0;
    if (kind == 2) {
        const unsigned char* p = (const unsigned char*)mask + warp * T_DIM;
        for (int t = lane; t < T_DIM; t += 32) cnt += (p[t] == 0);
    } else {
        const unsigned* p = dw + (size_t)warp * T_DIM;
        for (int t = lane; t < T_DIM; t += 32) cnt += (p[t] == 0u);
    }
    for (int o = 16; o > 0; o >>= 1) cnt += __shfl_down_sync(0xffffffffu, cnt, o);
    if (lane == 0) g_len[warp] = cnt;
}

// ---------------- K1: fused fp32 GEMM (FFMA2) + ReLU + proj + sigmoid -------
// Same structure as the passing R1 kernel; inner 8x8 microkernel now uses
// fma.rn.f32x2 (32 packed FMAs instead of 64 scalar FMAs per k-step).
#define BMT 128
#define BNT 128
#define BKT 16
#define KTILES (K_DIM / BKT)   // 32
#define AS_STR (BMT + 4)

__global__ __launch_bounds__(256, 2) void k1_gemm(
    const float* __restrict__ A,   // [M][K] row-major (enc, m = t*B+b)
    const float* __restrict__ W1,  // [K][N] row-major
    const float* __restrict__ b1,  // [N]
    const float* __restrict__ w2,  // [N]
    const float* __restrict__ b2)  // [1]
{
    __shared__ float As[2][BKT][AS_STR];
    __shared__ __align__(16) float Bs[2][BKT][BNT];
    __shared__ float red[BMT][17];

    const int tid = threadIdx.x;
    const int tx = tid & 15, ty = tid >> 4;
    const int m0 = blockIdx.x * BMT;

    const int aRow0 = tid >> 2;
    const int aRow1 = aRow0 + 64;
    const int aCol  = (tid & 3) * 4;
    const int bRow0 = tid >> 5;
    const int bRow1 = bRow0 + 8;
    const int bCol  = (tid & 31) * 4;

    float rowacc[8];
#pragma unroll
    for (int i = 0; i < 8; i++) rowacc[i] = 0.f;
    const float b2s = b2[0];

    for (int n0 = 0; n0 < N_DIM; n0 += BNT) {
        u64 acc2[8][4];
#pragma unroll
        for (int i = 0; i < 8; i++)
#pragma unroll
            for (int j = 0; j < 4; j++) acc2[i][j] = 0ull;

        float4 aR0, aR1, bR0, bR1;
        aR0 = *(const float4*)(A + (size_t)(m0 + aRow0) * K_DIM + aCol);
        aR1 = *(const float4*)(A + (size_t)(m0 + aRow1) * K_DIM + aCol);
        bR0 = *(const float4*)(W1 + (size_t)bRow0 * N_DIM + n0 + bCol);
        bR1 = *(const float4*)(W1 + (size_t)bRow1 * N_DIM + n0 + bCol);
        As[0][aCol + 0][aRow0] = aR0.x; As[0][aCol + 1][aRow0] = aR0.y;
        As[0][aCol + 2][aRow0] = aR0.z; As[0][aCol + 3][aRow0] = aR0.w;
        As[0][aCol + 0][aRow1] = aR1.x; As[0][aCol + 1][aRow1] = aR1.y;
        As[0][aCol + 2][aRow1] = aR1.z; As[0][aCol + 3][aRow1] = aR1.w;
        *(float4*)&Bs[0][bRow0][bCol] = bR0;
        *(float4*)&Bs[0][bRow1][bCol] = bR1;
        __syncthreads();

        for (int kt = 0; kt < KTILES; kt++) {
            const int cur = kt & 1;
            if (kt + 1 < KTILES) {
                const int kb = (kt + 1) * BKT;
                aR0 = *(const float4*)(A + (size_t)(m0 + aRow0) * K_DIM + kb + aCol);
                aR1 = *(const float4*)(A + (size_t)(m0 + aRow1) * K_DIM + kb + aCol);
                bR0 = *(const float4*)(W1 + (size_t)(kb + bRow0) * N_DIM + n0 + bCol);
                bR1 = *(const float4*)(W1 + (size_t)(kb + bRow1) * N_DIM + n0 + bCol);
            }
#pragma unroll
            for (int kk = 0; kk < BKT; kk++) {
                float4 a0 = *(const float4*)&As[cur][kk][ty * 8];
                float4 a1 = *(const float4*)&As[cur][kk][ty * 8 + 4];
                const u64* bp = (const u64*)&Bs[cur][kk][tx * 8];
                u64 b0 = bp[0], b1v = bp[1], b2v = bp[2], b3 = bp[3];
                float av[8] = {a0.x, a0.y, a0.z, a0.w, a1.x, a1.y, a1.z, a1.w};
#pragma unroll
                for (int i = 0; i < 8; i++) {
                    u64 ad = dupf(av[i]);
                    acc2[i][0] = fma2(ad, b0,  acc2[i][0]);
                    acc2[i][1] = fma2(ad, b1v, acc2[i][1]);
                    acc2[i][2] = fma2(ad, b2v, acc2[i][2]);
                    acc2[i][3] = fma2(ad, b3,  acc2[i][3]);
                }
            }
            if (kt + 1 < KTILES) {
                const int nb = cur ^ 1;
                As[nb][aCol + 0][aRow0] = aR0.x; As[nb][aCol + 1][aRow0] = aR0.y;
                As[nb][aCol + 2][aRow0] = aR0.z; As[nb][aCol + 3][aRow0] = aR0.w;
                As[nb][aCol + 0][aRow1] = aR1.x; As[nb][aCol + 1][aRow1] = aR1.y;
                As[nb][aCol + 2][aRow1] = aR1.z; As[nb][aCol + 3][aRow1] = aR1.w;
                *(float4*)&Bs[nb][bRow0][bCol] = bR0;
                *(float4*)&Bs[nb][bRow1][bCol] = bR1;
                __syncthreads();
            }
        }

        // fused epilogue for this n-tile: relu(h + b1) * w2 -> row partials
        float b1r[8], w2r[8];
#pragma unroll
        for (int j = 0; j < 8; j++) {
            b1r[j] = b1[n0 + tx * 8 + j];
            w2r[j] = w2[n0 + tx * 8 + j];
        }
#pragma unroll
        for (int i = 0; i < 8; i++)
#pragma unroll
            for (int j2 = 0; j2 < 4; j2++) {
                float clo, chi;
                unpk(acc2[i][j2], clo, chi);
                float h0 = fmaxf(clo + b1r[j2 * 2], 0.f);
                float h1 = fmaxf(chi + b1r[j2 * 2 + 1], 0.f);
                rowacc[i] = fmaf(h0, w2r[j2 * 2], rowacc[i]);
                rowacc[i] = fmaf(h1, w2r[j2 * 2 + 1], rowacc[i]);
            }
        __syncthreads();
    }

    // reduce rowacc across the 16 tx threads of each row (fixed order)
#pragma unroll
    for (int i = 0; i < 8; i++) red[ty * 8 + i][tx] = rowacc[i];
    __syncthreads();
    if (tid < BMT) {
        float s = 0.f;
#pragma unroll
        for (int x = 0; x < 16; x++) s += red[tid][x];
        float arg = s + b2s;
        g_w[m0 + tid] = 1.0f / (1.0f + expf(-arg));
    }
}

// ---------------- K2: scalar CIF scan per batch -----------------------------
__global__ void k2_scan(float* __restrict__ out_marks,
                        float* __restrict__ out_quantity,
                        int write_extras)
{
    const int b = blockIdx.x;
    const int lane = threadIdx.x;
    const int L = g_len[b];

    float prev_w = 0.f, quantity = 0.f, seg_c0 = 0.f, last_w = 0.f;
    int seg_t0 = 0, r = 0;

    for (int chunk = 0; chunk < T_DIM; chunk += 32) {
        float wv = g_w[(chunk + lane) * B_DIM + b];
        float mymark = 0.f;
#pragma unroll 1
        for (int j = 0; j < 32; j++) {
            const int t = chunk + j;
            float w = __shfl_sync(0xffffffffu, wv, j);
            float mark = 0.f;
            if (t < L) {
                quantity += w;
                if (t == 0) seg_c0 = w;
                bool fired = (prev_w + w >= 1.0f);
                if (fired) {
                    float remained = 1.0f - prev_w;
                    if (lane == 0) {
                        int idx = b * T_DIM + r;
                        g_rt0[idx] = seg_t0; g_rt1[idx] = t;
                        g_rc0[idx] = seg_c0; g_rc1[idx] = remained;
                        g_rmult[idx] = 1.0f;
                    }
                    r++;
                    prev_w = w - remained;
                    seg_t0 = t;
                    seg_c0 = w - remained;
                    mark = 1.f;
                } else {
                    prev_w = w + prev_w;
                }
                last_w = w;
            } else if (t == L) {
                if (prev_w > 0.6f) {
                    if (lane == 0) {
                        int idx = b * T_DIM + r;
                        g_rt0[idx] = seg_t0; g_rt1[idx] = L - 1;
                        g_rc0[idx] = seg_c0; g_rc1[idx] = last_w;
                        g_rmult[idx] = 1.0f / (prev_w + 1e-10f);
                    }
                    r++;
                    mark = 1.f;
                }
            }
            if (lane == j) mymark = mark;
        }
        if (write_extras) out_marks[b * T_DIM + chunk + lane] = mymark;
    }
    if (lane == 0) {
        g_nrows[b] = r;
        if (write_extras) out_quantity[b] = quantity;
    }
}

// ---------------- K3: segment sums in compacted order -----------------------
__global__ __launch_bounds__(128) void k3_rows(
    const float* __restrict__ x,
    float* __restrict__ out_cif,
    float* __restrict__ out_mask,
    int write_extras)
{
    const int r = blockIdx.x, b = blockIdx.y;
    const int tid = threadIdx.x;
    const int nr = g_nrows[b];

    float4 acc = make_float4(0.f, 0.f, 0.f, 0.f);
    if (r < nr) {
        const int idx = b * T_DIM + r;
        const int t0 = g_rt0[idx], t1 = g_rt1[idx];
        const float c0 = g_rc0[idx], c1 = g_rc1[idx], mult = g_rmult[idx];
        const float* xb = x + (size_t)b * E_DIM + tid * 4;
        const size_t tstride = (size_t)B_DIM * E_DIM;

        float4 v = *(const float4*)(xb + (size_t)t0 * tstride);
        acc.x = c0 * v.x; acc.y = c0 * v.y; acc.z = c0 * v.z; acc.w = c0 * v.w;
        for (int t = t0 + 1; t < t1; t++) {
            float w = g_w[t * B_DIM + b];
            v = *(const float4*)(xb + (size_t)t * tstride);
            acc.x = fmaf(w, v.x, acc.x); acc.y = fmaf(w, v.y, acc.y);
            acc.z = fmaf(w, v.z, acc.z); acc.w = fmaf(w, v.w, acc.w);
        }
        if (t1 > t0) {
            v = *(const float4*)(xb + (size_t)t1 * tstride);
            acc.x = fmaf(c1, v.x, acc.x); acc.y = fmaf(c1, v.y, acc.y);
            acc.z = fmaf(c1, v.z, acc.z); acc.w = fmaf(c1, v.w, acc.w);
        }
        acc.x *= mult; acc.y *= mult; acc.z *= mult; acc.w *= mult;
    }
    *(float4*)(out_cif + ((size_t)(b * T_DIM + r)) * E_DIM + tid * 4) = acc;
    if (write_extras && tid == 0) out_mask[b * T_DIM + r] = (r < nr) ? 1.f : 0.f;
}

// ---------------- launch ----------------------------------------------------
extern "C" void kernel_launch(void* const* d_in, const int* in_sizes, int n_in,
                              void* d_out, int out_size)
{
    const float* enc = (const float*)d_in[0];
    const void*  mask = d_in[1];
    const float* dense_w = (const float*)d_in[2];
    const float* dense_b = (const float*)d_in[3];
    const float* wproj_w = (const float*)d_in[4];
    const float* wproj_b = (const float*)d_in[5];
    float* out = (float*)d_out;

    const int cif_elems = B_DIM * T_DIM * E_DIM;
    const int full = cif_elems + B_DIM * T_DIM + B_DIM + B_DIM * T_DIM;
    const int extras = (out_size >= full) ? 1 : 0;

    float* out_mask   = out + cif_elems;
    float* out_q      = out_mask + B_DIM * T_DIM;
    float* out_marks  = out_q + B_DIM;

    k0_mask<<<1, 1024>>>(mask);
    k1_gemm<<<M_DIM / BMT, 256>>>(enc, dense_w, dense_b, wproj_w, wproj_b);
    k2_scan<<<B_DIM, 32>>>(out_marks, out_q, extras);
    k3_rows<<<dim3(T_DIM, B_DIM), 128>>>(enc, out, out_mask, extras);
}